// round 13
// baseline (speedup 1.0000x reference)
#include <cuda_runtime.h>
#include <cuda_fp16.h>
#include <math.h>
#include <stdint.h>

// ======================= scratch (static, allocation-free) =======================
static __device__ __half g_Xh[8192UL * 512];
static __device__ __half g_Wh[3UL * 512 * 512];
static __device__ __half g_Qh[8192UL * 512];
static __device__ __half g_Kh[8192UL * 512];
static __device__ __half g_Vth[512UL * 8192];
static __device__ __half g_Ph[4UL * 2048 * 2048];

// tcgen05 path only exists in the sm_103a compilation pass
#if defined(__CUDA_ARCH__) && (defined(__CUDA_ARCH_FEAT_SM103_ALL) || \
    (defined(__CUDA_ARCH_SPECIFIC__) && (__CUDA_ARCH_SPECIFIC__ == 1030)))
#define TC_PATH 1
#else
#define TC_PATH 0
#endif

// ======================= common helpers =======================
__device__ __forceinline__ uint32_t smem_u32(const void* p) {
    uint32_t a;
    asm("{ .reg .u64 t; cvta.to.shared.u64 t, %1; cvt.u32.u64 %0, t; }" : "=r"(a) : "l"(p));
    return a;
}
__device__ __forceinline__ void ldsm_x4(uint32_t r[4], uint32_t addr) {
    asm volatile("ldmatrix.sync.aligned.m8n8.x4.shared.b16 {%0,%1,%2,%3}, [%4];"
                 : "=r"(r[0]), "=r"(r[1]), "=r"(r[2]), "=r"(r[3]) : "r"(addr));
}
__device__ __forceinline__ void hmma(float* c, const uint32_t* a, const uint32_t* b) {
    asm volatile(
        "mma.sync.aligned.m16n8k16.row.col.f32.f16.f16.f32 "
        "{%0,%1,%2,%3}, {%4,%5,%6,%7}, {%8,%9}, {%0,%1,%2,%3};"
        : "+f"(c[0]), "+f"(c[1]), "+f"(c[2]), "+f"(c[3])
        : "r"(a[0]), "r"(a[1]), "r"(a[2]), "r"(a[3]), "r"(b[0]), "r"(b[1]));
}
__device__ __forceinline__ void cp16(uint32_t s, const void* g) {
    asm volatile("cp.async.cg.shared.global [%0], [%1], 16;" :: "r"(s), "l"(g) : "memory");
}

#if TC_PATH
__device__ __forceinline__ uint32_t elect_one() {
    uint32_t pred;
    asm volatile("{ .reg .pred p; elect.sync _|p, 0xFFFFFFFF; selp.b32 %0, 1, 0, p; }" : "=r"(pred));
    return pred;
}
#define MBAR_INIT(a, n) asm volatile("mbarrier.init.shared.b64 [%0], %1;" :: "r"(a), "r"(n) : "memory")
#define MBAR_INVAL(a)   asm volatile("mbarrier.inval.shared.b64 [%0];" :: "r"(a) : "memory")
#define MBAR_WAIT(addr, par) do {                                               \
    uint32_t _m = (addr), _p = (par), _d;                                       \
    asm volatile("{ .reg .pred p;"                                              \
        " mbarrier.try_wait.parity.acquire.cta.shared::cta.b64 p, [%1], %2;"    \
        " selp.b32 %0, 1, 0, p; }" : "=r"(_d) : "r"(_m), "r"(_p) : "memory");   \
    if (!_d) {                                                                  \
        asm volatile("{ .reg .pred P1;"                                         \
            " WL_%=:"                                                           \
            " mbarrier.try_wait.parity.acquire.cta.shared::cta.b64 P1, [%0], %1, 0x989680;" \
            " @P1 bra.uni WD_%=;"                                               \
            " bra.uni WL_%=;"                                                   \
            " WD_%=: }" :: "r"(_m), "r"(_p) : "memory");                        \
    }                                                                           \
} while (0)

// SW128 K-major descriptor: layout=SW128(2), version=1, SBO=64, LBO=1
__device__ __forceinline__ uint64_t make_desc(uint32_t addr) {
    const uint64_t base = (uint64_t(2) << 61) | (uint64_t(1) << 46) |
                          (uint64_t(64) << 32) | (uint64_t(1) << 16);
    return base | ((uint64_t)(addr >> 4) & 0x3FFF);
}
// idesc: F32 accum (1<<4), fp16 A/B (0), N=128 (16<<17), M=128 (8<<24)
#define TC_IDESC ((1u << 4) | (16u << 17) | (8u << 24))

__device__ __forceinline__ void mma_f16_ss(uint32_t d, uint64_t a, uint64_t b, uint32_t en) {
    asm volatile(
        "{ .reg .pred p; setp.ne.u32 p, %5, 0;"
        " tcgen05.mma.cta_group::1.kind::f16 [%0], %1, %2, %3, {%4,%4,%4,%4}, p; }"
        :: "r"(d), "l"(a), "l"(b), "r"(TC_IDESC), "r"(0u), "r"(en) : "memory");
}
#define TC_COMMIT(mb) asm volatile( \
    "tcgen05.commit.cta_group::1.mbarrier::arrive::one.shared::cluster.b64 [%0];" \
    :: "r"(mb) : "memory")
#define TC_LD_X32(r, a) asm volatile( \
    "tcgen05.ld.sync.aligned.32x32b.x32.b32 " \
    "{%0,%1,%2,%3,%4,%5,%6,%7,%8,%9,%10,%11,%12,%13,%14,%15," \
    "%16,%17,%18,%19,%20,%21,%22,%23,%24,%25,%26,%27,%28,%29,%30,%31}, [%32];" \
    : "=r"((r)[0]),"=r"((r)[1]),"=r"((r)[2]),"=r"((r)[3]),"=r"((r)[4]),"=r"((r)[5]),"=r"((r)[6]),"=r"((r)[7]), \
      "=r"((r)[8]),"=r"((r)[9]),"=r"((r)[10]),"=r"((r)[11]),"=r"((r)[12]),"=r"((r)[13]),"=r"((r)[14]),"=r"((r)[15]), \
      "=r"((r)[16]),"=r"((r)[17]),"=r"((r)[18]),"=r"((r)[19]),"=r"((r)[20]),"=r"((r)[21]),"=r"((r)[22]),"=r"((r)[23]), \
      "=r"((r)[24]),"=r"((r)[25]),"=r"((r)[26]),"=r"((r)[27]),"=r"((r)[28]),"=r"((r)[29]),"=r"((r)[30]),"=r"((r)[31]) \
    : "r"(a))
#endif  // TC_PATH

// =============================================================================
// unified GEMM, 128 threads:
//   EPI 2: tile 128x256, C = alpha * A@B^T, f32 out     [scores / weighted]
//   EPI 3: tile 128x128, fused QKV: sec = blockIdx.x>>2, n0 = (blockIdx.x&3)*128
//          sec 0 -> Qh, sec 1 -> Kh (fp16 + bias), sec 2 -> Vth (transposed)
// TC path: tcgen05 SS MMA (2 x N=128 per K-step for EPI2), TMEM accumulator,
//          2-stage cp.async pipeline
// fallback: HMMA warp 64x64, 3-stage cp.async; EPI2 runs two 128-wide halves
// =============================================================================
#define SMEM_G 100352

template <int EPI>
__global__ void __launch_bounds__(128, 2)
gemm128(const __half* __restrict__ A, const __half* __restrict__ B,
        const float* __restrict__ bias_q, const float* __restrict__ bias_k,
        const float* __restrict__ bias_v,
        float* __restrict__ Cf,
        __half* __restrict__ ChQ, __half* __restrict__ ChK, __half* __restrict__ ChV,
        int K, int lda, int ldb, int ldc,
        long sA, long sB, long sC, float alpha)
{
    constexpr int NT = (EPI == 2) ? 256 : 128;
    constexpr int NHALF = NT / 128;

    extern __shared__ char smem_raw[];
    const uint32_t raw32 = smem_u32(smem_raw);
    const uint32_t sbase = (raw32 + 1023) & ~1023u;
    char* smem_al = smem_raw + (sbase - raw32);

    const int tid = threadIdx.x;
    const int w = tid >> 5, l = tid & 31;
    const int m0 = blockIdx.y * 128;
    const int z = blockIdx.z;

    // output / operand decode
    int n0;
    const __half* Bb;
    const float* biasp = nullptr;
    __half* Chp = nullptr;
    bool tr = false;
    int ldce = ldc;
    if (EPI == 3) {
        int sec = blockIdx.x >> 2;
        n0 = (blockIdx.x & 3) << 7;
        Bb = B + (long)sec * 262144;
        biasp = (sec == 0) ? bias_q : (sec == 1) ? bias_k : bias_v;
        Chp = (sec == 0) ? ChQ : (sec == 1) ? ChK : ChV;
        tr = (sec == 2);
        ldce = tr ? 8192 : 512;
    } else {
        n0 = blockIdx.x * NT;
        Bb = B + z * sB;
    }
    const __half* Ab = A + z * sA;

#if TC_PATH
    // ---------------- tcgen05 path: 2-stage pipeline, NT-wide tile ----------------
    constexpr int STGSZ = 16384 + NT * 128;          // A 16KB + B NT*128B
    constexpr int NLD = (1024 + NT * 8) / 128;       // cp16 per thread per stage
    const uint32_t TM_PTR = sbase;
    const uint32_t MB = sbase + 8;                   // mbars at +8, +16
    const uint32_t TILES = sbase + 1024;

    if (w == 0) {
        asm volatile("tcgen05.alloc.cta_group::1.sync.aligned.shared::cta.b32 [%0], %1;"
                     :: "r"(TM_PTR), "r"((uint32_t)NT) : "memory");
        asm volatile("tcgen05.relinquish_alloc_permit.cta_group::1.sync.aligned;");
    }
    if (tid == 0) { MBAR_INIT(MB, 1); MBAR_INIT(MB + 8, 1); }
    __syncthreads();
    uint32_t tmem;
    asm volatile("ld.shared.b32 %0, [%1];" : "=r"(tmem) : "r"(TM_PTR));

    auto load_stage = [&](int c) {
        const uint32_t stg = TILES + (c & 1) * STGSZ;
        #pragma unroll
        for (int i = 0; i < NLD; i++) {
            int id = tid + i * 128;
            const __half* g;
            uint32_t roff;
            int row, ch;
            if (id < 1024) {                          // A: 128 rows x 8 chunks
                row = id >> 3; ch = id & 7;
                g = Ab + (long)(m0 + row) * lda + (long)c * 64 + ch * 8;
                roff = 0;
            } else {                                  // B: NT rows x 8 chunks
                int rem = id - 1024;
                row = rem >> 3; ch = rem & 7;
                g = Bb + (long)(n0 + row) * ldb + (long)c * 64 + ch * 8;
                roff = 16384;
            }
            uint32_t o = row * 128 + ch * 16;
            uint32_t sa = stg + roff + (o ^ ((o >> 3) & 0x70));
            cp16(sa, g);
        }
        asm volatile("cp.async.commit_group;" ::: "memory");
    };

    const int NC = K / 64;
    int pha[2] = {0, 0};

    load_stage(0);
    for (int c = 0; c < NC; c++) {
        if (c + 1 < NC) {
            int s2 = (c + 1) & 1;
            if (c + 1 >= 2) { MBAR_WAIT(MB + s2 * 8, pha[s2]); pha[s2] ^= 1; }
            load_stage(c + 1);
            asm volatile("cp.async.wait_group 1;" ::: "memory");
        } else {
            asm volatile("cp.async.wait_group 0;" ::: "memory");
        }
        __syncthreads();
        if (w == 0) {
            asm volatile("fence.proxy.async.shared::cta;" ::: "memory");
            if (elect_one()) {
                const uint32_t stg = TILES + (c & 1) * STGSZ;
                uint64_t dA = make_desc(stg);
                uint64_t dB0 = make_desc(stg + 16384);
                #pragma unroll
                for (int ks = 0; ks < 4; ks++) {
                    uint32_t en = (c != 0) || (ks != 0);
                    mma_f16_ss(tmem, dA + ks * 2, dB0 + ks * 2, en);
                    if (NHALF == 2) {
                        uint64_t dB1 = make_desc(stg + 32768);
                        mma_f16_ss(tmem + 128, dA + ks * 2, dB1 + ks * 2, en);
                    }
                }
                TC_COMMIT(MB + (c & 1) * 8);
            }
        }
    }
    { int s = (NC - 2) & 1; MBAR_WAIT(MB + s * 8, pha[s]); pha[s] ^= 1;
      s = (NC - 1) & 1;     MBAR_WAIT(MB + s * 8, pha[s]); pha[s] ^= 1; }
    asm volatile("tcgen05.fence::after_thread_sync;" ::: "memory");
    __syncthreads();

    // epilogue per 128-col half: TMEM -> sf -> GMEM (stage SMEM is dead; reuse)
    float* sf = reinterpret_cast<float*>(smem_al + 1024);
    const int mrow = w * 32 + l;
    #pragma unroll
    for (int h = 0; h < NHALF; h++) {
        const int n0h = n0 + h * 128;
        #pragma unroll
        for (int c0 = 0; c0 < 128; c0 += 32) {
            uint32_t r[32];
            TC_LD_X32(r, tmem + h * 128 + c0);
            asm volatile("tcgen05.wait::ld.sync.aligned;" ::: "memory");
            #pragma unroll
            for (int j = 0; j < 32; j++) {
                float v = __uint_as_float(r[j]) * alpha;
                if (EPI == 3) v += biasp[n0h + c0 + j];
                if (EPI == 3 && tr) sf[(c0 + j) * 129 + mrow] = v;
                else                sf[mrow * 129 + c0 + j] = v;
            }
        }
        __syncthreads();
        if (EPI == 2) {
            float* Cb = Cf + z * sC;
            #pragma unroll
            for (int i = 0; i < 32; i++) {
                int idx = (tid + i * 128) << 2;
                int row = idx >> 7, col = idx & 127;
                const float* p = &sf[row * 129 + col];
                float4 v = make_float4(p[0], p[1], p[2], p[3]);
                *reinterpret_cast<float4*>(Cb + (long)(m0 + row) * ldc + n0h + col) = v;
            }
        } else {
            #pragma unroll
            for (int i = 0; i < 32; i++) {
                int idx = (tid + i * 128) << 2;
                int row = idx >> 7, col = idx & 127;
                const float* p = &sf[row * 129 + col];
                uint32_t hp[2];
                #pragma unroll
                for (int q = 0; q < 2; q++) {
                    __half2 H = __halves2half2(__float2half_rn(p[2 * q]),
                                               __float2half_rn(p[2 * q + 1]));
                    hp[q] = *reinterpret_cast<uint32_t*>(&H);
                }
                long dst = tr ? ((long)(n0h + row) * (long)ldce + m0 + col)
                              : ((long)(m0 + row) * (long)ldce + n0h + col);
                *reinterpret_cast<uint2*>(Chp + dst) = make_uint2(hp[0], hp[1]);
            }
        }
        __syncthreads();
    }
    if (tid == 0) { MBAR_INVAL(MB); MBAR_INVAL(MB + 8); }
    if (w == 0)
        asm volatile("tcgen05.dealloc.cta_group::1.sync.aligned.b32 %0, %1;"
                     :: "r"(tmem), "r"((uint32_t)NT));

#else
    // ---------------- HMMA fallback: NHALF sequential 128-wide passes ----------------
    const int NC = K / 32;
    float* sf = reinterpret_cast<float*>(smem_al);

    for (int h = 0; h < NHALF; h++) {
        const int n0h = n0 + h * 128;

        auto load_stage = [&](int c) {
            const uint32_t stg = sbase + (c % 3) * 16384;
            #pragma unroll
            for (int i = 0; i < 8; i++) {
                int id = tid + i * 128;
                int t = id >> 9, rem = id & 511, row = rem >> 2, ch = rem & 3;
                const __half* g = (t == 0)
                    ? Ab + (long)(m0 + row) * lda + (long)c * 32 + ch * 8
                    : Bb + (long)(n0h + row) * ldb + (long)c * 32 + ch * 8;
                uint32_t sa = stg + t * 8192 + row * 64 + ((ch ^ ((row >> 1) & 3)) << 4);
                cp16(sa, g);
            }
            asm volatile("cp.async.commit_group;" ::: "memory");
        };

        float acc[4][8][4] = {};
        const int wm = (w & 1) * 64;
        const int wn = (w >> 1) * 64;
        const int matI = l >> 3, rim = l & 7;

        uint32_t fB[2][4][4];
        uint32_t fA[2][4];

        auto ldB = [&](int buf, uint32_t bbase, int kk) {
            #pragma unroll
            for (int p = 0; p < 4; p++) {
                int n = wn + p * 16 + (matI >> 1) * 8 + rim;
                int ch = kk * 2 + (matI & 1);
                ldsm_x4(fB[buf][p], bbase + n * 64 + ((ch ^ ((n >> 1) & 3)) << 4));
            }
        };
        auto ldA = [&](int buf, uint32_t stg, int kk, int mi) {
            int row = wm + mi * 16 + rim + (matI & 1) * 8;
            int ch = kk * 2 + (matI >> 1);
            ldsm_x4(fA[buf], stg + row * 64 + ((ch ^ ((row >> 1) & 3)) << 4));
        };

        load_stage(0);
        load_stage(1);

        for (int c = 0; c < NC; c++) {
            asm volatile("cp.async.wait_group 1;" ::: "memory");
            __syncthreads();
            if (c + 2 < NC) load_stage(c + 2);
            else asm volatile("cp.async.commit_group;" ::: "memory");

            const uint32_t stg = sbase + (c % 3) * 16384;
            const uint32_t bbase = stg + 8192;

            ldB(0, bbase, 0);
            ldA(0, stg, 0, 0);

            #pragma unroll
            for (int kk = 0; kk < 2; kk++) {
                #pragma unroll
                for (int mi = 0; mi < 4; mi++) {
                    const int cur = mi & 1;
                    if (mi < 3) {
                        ldA(cur ^ 1, stg, kk, mi + 1);
                    } else if (kk == 0) {
                        ldB(1, bbase, 1);
                        ldA(cur ^ 1, stg, 1, 0);
                    }
                    #pragma unroll
                    for (int ni = 0; ni < 8; ni++)
                        hmma(acc[mi][ni], fA[cur], &fB[kk][ni >> 1][(ni & 1) * 2]);
                }
            }
        }
        asm volatile("cp.async.wait_group 0;" ::: "memory");
        __syncthreads();

        {
            const int r_ = l >> 2, cq = (l & 3) * 2;
            #pragma unroll
            for (int mi = 0; mi < 4; mi++)
                #pragma unroll
                for (int ni = 0; ni < 8; ni++) {
                    int m = wm + mi * 16 + r_;
                    int n = wn + ni * 8 + cq;
                    float b0 = 0.f, b1 = 0.f;
                    if (EPI == 3) { b0 = biasp[n0h + n]; b1 = biasp[n0h + n + 1]; }
                    float v00 = acc[mi][ni][0] * alpha + b0;
                    float v01 = acc[mi][ni][1] * alpha + b1;
                    float v10 = acc[mi][ni][2] * alpha + b0;
                    float v11 = acc[mi][ni][3] * alpha + b1;
                    if (EPI == 3 && tr) {
                        sf[n * 129 + m] = v00;       sf[(n + 1) * 129 + m] = v01;
                        sf[n * 129 + m + 8] = v10;   sf[(n + 1) * 129 + m + 8] = v11;
                    } else {
                        sf[m * 129 + n] = v00;       sf[m * 129 + n + 1] = v01;
                        sf[(m + 8) * 129 + n] = v10; sf[(m + 8) * 129 + n + 1] = v11;
                    }
                }
        }
        __syncthreads();

        if (EPI == 2) {
            float* Cb = Cf + z * sC;
            #pragma unroll
            for (int i = 0; i < 32; i++) {
                int idx = (tid + i * 128) << 2;
                int row = idx >> 7, col = idx & 127;
                const float* p = &sf[row * 129 + col];
                float4 v = make_float4(p[0], p[1], p[2], p[3]);
                *reinterpret_cast<float4*>(Cb + (long)(m0 + row) * ldc + n0h + col) = v;
            }
        } else {
            #pragma unroll
            for (int i = 0; i < 32; i++) {
                int idx = (tid + i * 128) << 2;
                int row = idx >> 7, col = idx & 127;
                const float* p = &sf[row * 129 + col];
                uint32_t hp[2];
                #pragma unroll
                for (int q = 0; q < 2; q++) {
                    __half2 H = __halves2half2(__float2half_rn(p[2 * q]),
                                               __float2half_rn(p[2 * q + 1]));
                    hp[q] = *reinterpret_cast<uint32_t*>(&H);
                }
                long dst = tr ? ((long)(n0h + row) * (long)ldce + m0 + col)
                              : ((long)(m0 + row) * (long)ldce + n0h + col);
                *reinterpret_cast<uint2*>(Chp + dst) = make_uint2(hp[0], hp[1]);
            }
        }
        __syncthreads();
    }
#endif
}

// ======================= single fused conversion: x + Wq + Wk + Wv -> fp16 =======================
__global__ void cvt_all(const float* __restrict__ x,
                        const float* __restrict__ Wq, const float* __restrict__ Wk,
                        const float* __restrict__ Wv,
                        __half* __restrict__ Xh, __half* __restrict__ Wh,
                        int NX4, int NW4)
{
    int i = blockIdx.x * blockDim.x + threadIdx.x;
    if (i < NX4) {
        float4 v = reinterpret_cast<const float4*>(x)[i];
        __half2 h0 = __floats2half2_rn(v.x, v.y), h1 = __floats2half2_rn(v.z, v.w);
        reinterpret_cast<uint2*>(Xh)[i] = make_uint2(*(uint32_t*)&h0, *(uint32_t*)&h1);
    } else {
        int k = i - NX4;
        if (k >= 3 * NW4) return;
        int s = k / NW4;
        int j = k - s * NW4;
        const float* src = (s == 0) ? Wq : (s == 1) ? Wk : Wv;
        float4 v = reinterpret_cast<const float4*>(src)[j];
        __half2 h0 = __floats2half2_rn(v.x, v.y), h1 = __floats2half2_rn(v.z, v.w);
        reinterpret_cast<uint2*>(Wh)[k] = make_uint2(*(uint32_t*)&h0, *(uint32_t*)&h1);
    }
}

// ======================= softmax: 128 threads/row, 4x float4 ILP =======================
__global__ void __launch_bounds__(128) softmax_kernel(
    float* __restrict__ att, __half* __restrict__ Ph)
{
    const int S = 2048;
    const long rowoff = (long)blockIdx.x * S;
    float4* row4 = reinterpret_cast<float4*>(att + rowoff);
    const int t = threadIdx.x, lane = t & 31, warp = t >> 5;

    __shared__ float red_max[4], red_sum[4];

    float4 v[4];
    float vmax = -1e30f;
    #pragma unroll
    for (int i = 0; i < 4; i++) v[i] = row4[t + i * 128];
    #pragma unroll
    for (int i = 0; i < 4; i++)
        vmax = fmaxf(vmax, fmaxf(fmaxf(v[i].x, v[i].y), fmaxf(v[i].z, v[i].w)));
    #pragma unroll
    for (int o = 16; o > 0; o >>= 1) vmax = fmaxf(vmax, __shfl_xor_sync(~0u, vmax, o));
    if (lane == 0) red_max[warp] = vmax;
    __syncthreads();
    vmax = fmaxf(fmaxf(red_max[0], red_max[1]), fmaxf(red_max[2], red_max[3]));

    float sum = 0.f;
    #pragma unroll
    for (int i = 0; i < 4; i++) {
        v[i].x = __expf(v[i].x - vmax); v[i].y = __expf(v[i].y - vmax);
        v[i].z = __expf(v[i].z - vmax); v[i].w = __expf(v[i].w - vmax);
        sum += (v[i].x + v[i].y) + (v[i].z + v[i].w);
    }
    #pragma unroll
    for (int o = 16; o > 0; o >>= 1) sum += __shfl_xor_sync(~0u, sum, o);
    if (lane == 0) red_sum[warp] = sum;
    __syncthreads();
    float tot = (red_sum[0] + red_sum[1]) + (red_sum[2] + red_sum[3]);
    float inv = 1.0f / tot;

    uint2* Ph2 = reinterpret_cast<uint2*>(Ph + rowoff);
    #pragma unroll
    for (int i = 0; i < 4; i++) {
        float4 p;
        p.x = v[i].x * inv; p.y = v[i].y * inv;
        p.z = v[i].z * inv; p.w = v[i].w * inv;
        row4[t + i * 128] = p;
        __half2 a = __floats2half2_rn(p.x, p.y), b = __floats2half2_rn(p.z, p.w);
        Ph2[t + i * 128] = make_uint2(*(uint32_t*)&a, *(uint32_t*)&b);
    }
}

// ======================= launch =======================
extern "C" void kernel_launch(void* const* d_in, const int* in_sizes, int n_in,
                              void* d_out, int out_size)
{
    const float* x  = (const float*)d_in[0];
    const float* Wq = (const float*)d_in[1];
    const float* bq = (const float*)d_in[2];
    const float* Wk = (const float*)d_in[3];
    const float* bk = (const float*)d_in[4];
    const float* Wv = (const float*)d_in[5];
    const float* bv = (const float*)d_in[6];

    const int B = 4, S = 2048, D = 512;
    float* att = (float*)d_out;
    float* wtd = att + (size_t)B * S * S;

    __half *Xh, *Wh, *Qh, *Kh, *Vth, *Ph;
    cudaGetSymbolAddress((void**)&Xh, g_Xh);
    cudaGetSymbolAddress((void**)&Wh, g_Wh);
    cudaGetSymbolAddress((void**)&Qh, g_Qh);
    cudaGetSymbolAddress((void**)&Kh, g_Kh);
    cudaGetSymbolAddress((void**)&Vth, g_Vth);
    cudaGetSymbolAddress((void**)&Ph, g_Ph);

    cudaFuncSetAttribute(gemm128<2>, cudaFuncAttributeMaxDynamicSharedMemorySize, SMEM_G);
    cudaFuncSetAttribute(gemm128<3>, cudaFuncAttributeMaxDynamicSharedMemorySize, SMEM_G);

    const int NX4 = B * S * D / 4;       // 1048576
    const int NW4 = D * D / 4;           // 65536
    const int NALL = NX4 + 3 * NW4;
    cvt_all<<<(NALL + 255) / 256, 256>>>(x, Wq, Wk, Wv, Xh, Wh, NX4, NW4);

    // fused QKV projections (1-term fp16): Q, K normal; V transposed into Vth [512, 8192]
    dim3 gqkv(12, 64, 1);
    gemm128<3><<<gqkv, 128, SMEM_G>>>(Xh, Wh, bq, bk, bv, nullptr, Qh, Kh, Vth,
                                      D, D, D, D, 0, 0, 0, 1.0f);

    // scores: att[b] = Q[b] @ K[b]^T * scale   (tiles 128x256)
    const float scale = 1.0f / sqrtf((float)D);
    dim3 gsc(S / 256, S / 128, B);
    gemm128<2><<<gsc, 128, SMEM_G>>>(Qh, Kh, nullptr, nullptr, nullptr, att,
                                     nullptr, nullptr, nullptr,
                                     D, D, D, S,
                                     (long)S * D, (long)S * D, (long)S * S, scale);

    // softmax
    softmax_kernel<<<B * S, 128>>>(att, Ph);

    // weighted: wtd[b] = P[b] @ V[b]  (tiles 128x256; Vt is [512, 8192], col offset b*2048)
    dim3 gw(D / 256, S / 128, B);
    gemm128<2><<<gw, 128, SMEM_G>>>(Ph, Vth, nullptr, nullptr, nullptr, wtd,
                                    nullptr, nullptr, nullptr,
                                    S, S, 8192, D,
                                    (long)S * S, (long)S, (long)S * D, 1.0f);
}

// round 14
// speedup vs baseline: 1.0672x; 1.0672x over previous
#include <cuda_runtime.h>
#include <cuda_fp16.h>
#include <math.h>
#include <stdint.h>

// ======================= scratch (static, allocation-free) =======================
static __device__ __half g_Xh[8192UL * 512];
static __device__ __half g_Wh[3UL * 512 * 512];
static __device__ __half g_Qh[8192UL * 512];
static __device__ __half g_Kh[8192UL * 512];
static __device__ __half g_Vth[512UL * 8192];
static __device__ __half g_Ph[4UL * 2048 * 2048];

// tcgen05 path only exists in the sm_103a compilation pass
#if defined(__CUDA_ARCH__) && (defined(__CUDA_ARCH_FEAT_SM103_ALL) || \
    (defined(__CUDA_ARCH_SPECIFIC__) && (__CUDA_ARCH_SPECIFIC__ == 1030)))
#define TC_PATH 1
#else
#define TC_PATH 0
#endif

// ======================= common helpers =======================
__device__ __forceinline__ uint32_t smem_u32(const void* p) {
    uint32_t a;
    asm("{ .reg .u64 t; cvta.to.shared.u64 t, %1; cvt.u32.u64 %0, t; }" : "=r"(a) : "l"(p));
    return a;
}
__device__ __forceinline__ void ldsm_x4(uint32_t r[4], uint32_t addr) {
    asm volatile("ldmatrix.sync.aligned.m8n8.x4.shared.b16 {%0,%1,%2,%3}, [%4];"
                 : "=r"(r[0]), "=r"(r[1]), "=r"(r[2]), "=r"(r[3]) : "r"(addr));
}
__device__ __forceinline__ void hmma(float* c, const uint32_t* a, const uint32_t* b) {
    asm volatile(
        "mma.sync.aligned.m16n8k16.row.col.f32.f16.f16.f32 "
        "{%0,%1,%2,%3}, {%4,%5,%6,%7}, {%8,%9}, {%0,%1,%2,%3};"
        : "+f"(c[0]), "+f"(c[1]), "+f"(c[2]), "+f"(c[3])
        : "r"(a[0]), "r"(a[1]), "r"(a[2]), "r"(a[3]), "r"(b[0]), "r"(b[1]));
}
__device__ __forceinline__ void cp16(uint32_t s, const void* g) {
    asm volatile("cp.async.cg.shared.global [%0], [%1], 16;" :: "r"(s), "l"(g) : "memory");
}

#if TC_PATH
__device__ __forceinline__ uint32_t elect_one() {
    uint32_t pred;
    asm volatile("{ .reg .pred p; elect.sync _|p, 0xFFFFFFFF; selp.b32 %0, 1, 0, p; }" : "=r"(pred));
    return pred;
}
#define MBAR_INIT(a, n) asm volatile("mbarrier.init.shared.b64 [%0], %1;" :: "r"(a), "r"(n) : "memory")
#define MBAR_INVAL(a)   asm volatile("mbarrier.inval.shared.b64 [%0];" :: "r"(a) : "memory")
#define MBAR_WAIT(addr, par) do {                                               \
    uint32_t _m = (addr), _p = (par), _d;                                       \
    asm volatile("{ .reg .pred p;"                                              \
        " mbarrier.try_wait.parity.acquire.cta.shared::cta.b64 p, [%1], %2;"    \
        " selp.b32 %0, 1, 0, p; }" : "=r"(_d) : "r"(_m), "r"(_p) : "memory");   \
    if (!_d) {                                                                  \
        asm volatile("{ .reg .pred P1;"                                         \
            " WL_%=:"                                                           \
            " mbarrier.try_wait.parity.acquire.cta.shared::cta.b64 P1, [%0], %1, 0x989680;" \
            " @P1 bra.uni WD_%=;"                                               \
            " bra.uni WL_%=;"                                                   \
            " WD_%=: }" :: "r"(_m), "r"(_p) : "memory");                        \
    }                                                                           \
} while (0)

// SW128 K-major descriptor: layout=SW128(2), version=1, SBO=64, LBO=1
__device__ __forceinline__ uint64_t make_desc(uint32_t addr) {
    const uint64_t base = (uint64_t(2) << 61) | (uint64_t(1) << 46) |
                          (uint64_t(64) << 32) | (uint64_t(1) << 16);
    return base | ((uint64_t)(addr >> 4) & 0x3FFF);
}
// idesc: F32 accum (1<<4), fp16 A/B (0), N=128 (16<<17), M=128 (8<<24)
#define TC_IDESC ((1u << 4) | (16u << 17) | (8u << 24))

__device__ __forceinline__ void mma_f16_ss(uint32_t d, uint64_t a, uint64_t b, uint32_t en) {
    asm volatile(
        "{ .reg .pred p; setp.ne.u32 p, %5, 0;"
        " tcgen05.mma.cta_group::1.kind::f16 [%0], %1, %2, %3, {%4,%4,%4,%4}, p; }"
        :: "r"(d), "l"(a), "l"(b), "r"(TC_IDESC), "r"(0u), "r"(en) : "memory");
}
#define TC_COMMIT(mb) asm volatile( \
    "tcgen05.commit.cta_group::1.mbarrier::arrive::one.shared::cluster.b64 [%0];" \
    :: "r"(mb) : "memory")
#define TC_LD_X32(r, a) asm volatile( \
    "tcgen05.ld.sync.aligned.32x32b.x32.b32 " \
    "{%0,%1,%2,%3,%4,%5,%6,%7,%8,%9,%10,%11,%12,%13,%14,%15," \
    "%16,%17,%18,%19,%20,%21,%22,%23,%24,%25,%26,%27,%28,%29,%30,%31}, [%32];" \
    : "=r"((r)[0]),"=r"((r)[1]),"=r"((r)[2]),"=r"((r)[3]),"=r"((r)[4]),"=r"((r)[5]),"=r"((r)[6]),"=r"((r)[7]), \
      "=r"((r)[8]),"=r"((r)[9]),"=r"((r)[10]),"=r"((r)[11]),"=r"((r)[12]),"=r"((r)[13]),"=r"((r)[14]),"=r"((r)[15]), \
      "=r"((r)[16]),"=r"((r)[17]),"=r"((r)[18]),"=r"((r)[19]),"=r"((r)[20]),"=r"((r)[21]),"=r"((r)[22]),"=r"((r)[23]), \
      "=r"((r)[24]),"=r"((r)[25]),"=r"((r)[26]),"=r"((r)[27]),"=r"((r)[28]),"=r"((r)[29]),"=r"((r)[30]),"=r"((r)[31]) \
    : "r"(a))
#endif  // TC_PATH

// =============================================================================
// unified GEMM, 128 threads, tile 128x128, up to 3 CTA/SM:
//   EPI 2: C = alpha * A@B^T, f32 out                 [scores / weighted]
//   EPI 3: fused QKV: sec = blockIdx.x>>2, n0 = (blockIdx.x&3)*128
//          sec 0 -> Qh, sec 1 -> Kh (fp16 + bias), sec 2 -> Vth (transposed)
// TC path: tcgen05 SS MMA, TMEM accumulator, 2-stage cp.async pipeline
// fallback: HMMA warp 64x64 (compile-only insurance; never runs on sm_103a)
// =============================================================================
#define SMEM_G 68096   // 1024 align slack + 1024 hdr + 66048 sf (stages 2x32768 fit inside)

template <int EPI>
__global__ void __launch_bounds__(128, 3)
gemm128(const __half* __restrict__ A, const __half* __restrict__ B,
        const float* __restrict__ bias_q, const float* __restrict__ bias_k,
        const float* __restrict__ bias_v,
        float* __restrict__ Cf,
        __half* __restrict__ ChQ, __half* __restrict__ ChK, __half* __restrict__ ChV,
        int K, int lda, int ldb, int ldc,
        long sA, long sB, long sC, float alpha)
{
    extern __shared__ char smem_raw[];
    const uint32_t raw32 = smem_u32(smem_raw);
    const uint32_t sbase = (raw32 + 1023) & ~1023u;
    char* smem_al = smem_raw + (sbase - raw32);

    const int tid = threadIdx.x;
    const int w = tid >> 5, l = tid & 31;
    const int m0 = blockIdx.y * 128;
    const int z = blockIdx.z;

    // output / operand decode
    int n0;
    const __half* Bb;
    const float* biasp = nullptr;
    __half* Chp = nullptr;
    bool tr = false;
    int ldce = ldc;
    if (EPI == 3) {
        int sec = blockIdx.x >> 2;
        n0 = (blockIdx.x & 3) << 7;
        Bb = B + (long)sec * 262144;
        biasp = (sec == 0) ? bias_q : (sec == 1) ? bias_k : bias_v;
        Chp = (sec == 0) ? ChQ : (sec == 1) ? ChK : ChV;
        tr = (sec == 2);
        ldce = tr ? 8192 : 512;
    } else {
        n0 = blockIdx.x * 128;
        Bb = B + z * sB;
    }
    const __half* Ab = A + z * sA;

    float* sf;   // epilogue staging [128][129]

#if TC_PATH
    // ---------------- tcgen05 path: 2-stage pipeline ----------------
    const uint32_t TM_PTR = sbase;
    const uint32_t MB = sbase + 8;                 // two mbars: +8, +16
    const uint32_t TILES = sbase + 1024;           // stage s: +s*32768 (A +0, B +16384)

    if (w == 0) {
        asm volatile("tcgen05.alloc.cta_group::1.sync.aligned.shared::cta.b32 [%0], %1;"
                     :: "r"(TM_PTR), "r"(128u) : "memory");
        asm volatile("tcgen05.relinquish_alloc_permit.cta_group::1.sync.aligned;");
    }
    if (tid == 0) { MBAR_INIT(MB, 1); MBAR_INIT(MB + 8, 1); }
    __syncthreads();
    uint32_t tmem;
    asm volatile("ld.shared.b32 %0, [%1];" : "=r"(tmem) : "r"(TM_PTR));

    auto load_stage = [&](int c) {
        const uint32_t stg = TILES + (c & 1) * 32768;
        #pragma unroll
        for (int i = 0; i < 16; i++) {
            int id = tid + i * 128;                // 0..2047
            int t = id >> 10;                      // 0:A 1:B
            int rem = id & 1023;
            int row = rem >> 3, ch = rem & 7;      // 128 rows x 8 x 16B
            const __half* g = (t == 0)
                ? Ab + (long)(m0 + row) * lda + (long)c * 64 + ch * 8
                : Bb + (long)(n0 + row) * ldb + (long)c * 64 + ch * 8;
            uint32_t o = row * 128 + ch * 16;
            uint32_t sa = stg + t * 16384 + (o ^ ((o >> 3) & 0x70));
            cp16(sa, g);
        }
        asm volatile("cp.async.commit_group;" ::: "memory");
    };

    const int NC = K / 64;
    int pha[2] = {0, 0};

    load_stage(0);
    for (int c = 0; c < NC; c++) {
        if (c + 1 < NC) {
            int s2 = (c + 1) & 1;
            if (c + 1 >= 2) { MBAR_WAIT(MB + s2 * 8, pha[s2]); pha[s2] ^= 1; }
            load_stage(c + 1);
            asm volatile("cp.async.wait_group 1;" ::: "memory");
        } else {
            asm volatile("cp.async.wait_group 0;" ::: "memory");
        }
        __syncthreads();
        if (w == 0) {
            asm volatile("fence.proxy.async.shared::cta;" ::: "memory");
            if (elect_one()) {
                const uint32_t stg = TILES + (c & 1) * 32768;
                uint64_t dA = make_desc(stg), dB = make_desc(stg + 16384);
                #pragma unroll
                for (int ks = 0; ks < 4; ks++)
                    mma_f16_ss(tmem, dA + ks * 2, dB + ks * 2, (c != 0) || (ks != 0));
                TC_COMMIT(MB + (c & 1) * 8);
            }
        }
    }
    { int s = (NC - 2) & 1; MBAR_WAIT(MB + s * 8, pha[s]); pha[s] ^= 1;
      s = (NC - 1) & 1;     MBAR_WAIT(MB + s * 8, pha[s]); pha[s] ^= 1; }
    asm volatile("tcgen05.fence::after_thread_sync;" ::: "memory");
    __syncthreads();

    // TMEM -> sf (stage SMEM is dead; reuse it)
    sf = reinterpret_cast<float*>(smem_al + 1024);
    {
        const int mrow = w * 32 + l;
        #pragma unroll
        for (int c0 = 0; c0 < 128; c0 += 32) {
            uint32_t r[32];
            TC_LD_X32(r, tmem + c0);
            asm volatile("tcgen05.wait::ld.sync.aligned;" ::: "memory");
            #pragma unroll
            for (int j = 0; j < 32; j++) {
                float v = __uint_as_float(r[j]) * alpha;
                if (EPI == 3) v += biasp[n0 + c0 + j];
                if (EPI == 3 && tr) sf[(c0 + j) * 129 + mrow] = v;
                else                sf[mrow * 129 + c0 + j] = v;
            }
        }
    }
    __syncthreads();
    if (tid == 0) { MBAR_INVAL(MB); MBAR_INVAL(MB + 8); }
    if (w == 0)
        asm volatile("tcgen05.dealloc.cta_group::1.sync.aligned.b32 %0, %1;"
                     :: "r"(tmem), "r"(128u));

#else
    // ---------------- HMMA fallback (compile-only; never runs on sm_103a) ----------------
    const int NC = K / 32;

    auto load_stage = [&](int c) {
        const uint32_t stg = sbase + (c & 1) * 16384;
        #pragma unroll
        for (int i = 0; i < 8; i++) {
            int id = tid + i * 128;
            int t = id >> 9, rem = id & 511, row = rem >> 2, ch = rem & 3;
            const __half* g = (t == 0)
                ? Ab + (long)(m0 + row) * lda + (long)c * 32 + ch * 8
                : Bb + (long)(n0 + row) * ldb + (long)c * 32 + ch * 8;
            uint32_t sa = stg + t * 8192 + row * 64 + ((ch ^ ((row >> 1) & 3)) << 4);
            cp16(sa, g);
        }
        asm volatile("cp.async.commit_group;" ::: "memory");
    };

    float acc[4][8][4] = {};
    const int wm = (w & 1) * 64;
    const int wn = (w >> 1) * 64;
    const int matI = l >> 3, rim = l & 7;

    load_stage(0);
    load_stage(1);

    for (int c = 0; c < NC; c++) {
        asm volatile("cp.async.wait_group 1;" ::: "memory");
        __syncthreads();

        const uint32_t stg = sbase + (c & 1) * 16384;
        const uint32_t bbase = stg + 8192;
        #pragma unroll
        for (int kk = 0; kk < 2; kk++) {
            uint32_t fB[4][4];
            #pragma unroll
            for (int p = 0; p < 4; p++) {
                int n = wn + p * 16 + (matI >> 1) * 8 + rim;
                int ch = kk * 2 + (matI & 1);
                ldsm_x4(fB[p], bbase + n * 64 + ((ch ^ ((n >> 1) & 3)) << 4));
            }
            #pragma unroll
            for (int mi = 0; mi < 4; mi++) {
                int row = wm + mi * 16 + rim + (matI & 1) * 8;
                int ch = kk * 2 + (matI >> 1);
                uint32_t fA[4];
                ldsm_x4(fA, stg + row * 64 + ((ch ^ ((row >> 1) & 3)) << 4));
                #pragma unroll
                for (int ni = 0; ni < 8; ni++)
                    hmma(acc[mi][ni], fA, &fB[ni >> 1][(ni & 1) * 2]);
            }
        }
        __syncthreads();
        if (c + 2 < NC) load_stage(c + 2);
        else asm volatile("cp.async.commit_group;" ::: "memory");
    }
    asm volatile("cp.async.wait_group 0;" ::: "memory");
    __syncthreads();

    sf = reinterpret_cast<float*>(smem_al);
    {
        const int r_ = l >> 2, cq = (l & 3) * 2;
        #pragma unroll
        for (int mi = 0; mi < 4; mi++)
            #pragma unroll
            for (int ni = 0; ni < 8; ni++) {
                int m = wm + mi * 16 + r_;
                int n = wn + ni * 8 + cq;
                float b0 = 0.f, b1 = 0.f;
                if (EPI == 3) { b0 = biasp[n0 + n]; b1 = biasp[n0 + n + 1]; }
                float v00 = acc[mi][ni][0] * alpha + b0;
                float v01 = acc[mi][ni][1] * alpha + b1;
                float v10 = acc[mi][ni][2] * alpha + b0;
                float v11 = acc[mi][ni][3] * alpha + b1;
                if (EPI == 3 && tr) {
                    sf[n * 129 + m] = v00;       sf[(n + 1) * 129 + m] = v01;
                    sf[n * 129 + m + 8] = v10;   sf[(n + 1) * 129 + m + 8] = v11;
                } else {
                    sf[m * 129 + n] = v00;       sf[m * 129 + n + 1] = v01;
                    sf[(m + 8) * 129 + n] = v10; sf[(m + 8) * 129 + n + 1] = v11;
                }
            }
    }
    __syncthreads();
#endif

    // ---------------- common GMEM writes ----------------
    if (EPI == 2) {
        float* Cb = Cf + z * sC;
        #pragma unroll
        for (int i = 0; i < 32; i++) {
            int idx = (tid + i * 128) << 2;
            int row = idx >> 7, col = idx & 127;
            const float* p = &sf[row * 129 + col];
            float4 v = make_float4(p[0], p[1], p[2], p[3]);
            *reinterpret_cast<float4*>(Cb + (long)(m0 + row) * ldc + n0 + col) = v;
        }
    } else {
        #pragma unroll
        for (int i = 0; i < 32; i++) {
            int idx = (tid + i * 128) << 2;
            int row = idx >> 7, col = idx & 127;
            const float* p = &sf[row * 129 + col];
            uint32_t hp[2];
            #pragma unroll
            for (int q = 0; q < 2; q++) {
                __half2 H = __halves2half2(__float2half_rn(p[2 * q]),
                                           __float2half_rn(p[2 * q + 1]));
                hp[q] = *reinterpret_cast<uint32_t*>(&H);
            }
            long dst = tr ? ((long)(n0 + row) * (long)ldce + m0 + col)
                          : ((long)(m0 + row) * (long)ldce + n0 + col);
            *reinterpret_cast<uint2*>(Chp + dst) = make_uint2(hp[0], hp[1]);
        }
    }
}

// ======================= single fused conversion: x + Wq + Wk + Wv -> fp16 =======================
__global__ void cvt_all(const float* __restrict__ x,
                        const float* __restrict__ Wq, const float* __restrict__ Wk,
                        const float* __restrict__ Wv,
                        __half* __restrict__ Xh, __half* __restrict__ Wh,
                        int NX4, int NW4)
{
    int i = blockIdx.x * blockDim.x + threadIdx.x;
    if (i < NX4) {
        float4 v = reinterpret_cast<const float4*>(x)[i];
        __half2 h0 = __floats2half2_rn(v.x, v.y), h1 = __floats2half2_rn(v.z, v.w);
        reinterpret_cast<uint2*>(Xh)[i] = make_uint2(*(uint32_t*)&h0, *(uint32_t*)&h1);
    } else {
        int k = i - NX4;
        if (k >= 3 * NW4) return;
        int s = k / NW4;
        int j = k - s * NW4;
        const float* src = (s == 0) ? Wq : (s == 1) ? Wk : Wv;
        float4 v = reinterpret_cast<const float4*>(src)[j];
        __half2 h0 = __floats2half2_rn(v.x, v.y), h1 = __floats2half2_rn(v.z, v.w);
        reinterpret_cast<uint2*>(Wh)[k] = make_uint2(*(uint32_t*)&h0, *(uint32_t*)&h1);
    }
}

// ======================= softmax: 128 threads/row, 4x float4 ILP =======================
__global__ void __launch_bounds__(128) softmax_kernel(
    float* __restrict__ att, __half* __restrict__ Ph)
{
    const int S = 2048;
    const long rowoff = (long)blockIdx.x * S;
    float4* row4 = reinterpret_cast<float4*>(att + rowoff);
    const int t = threadIdx.x, lane = t & 31, warp = t >> 5;

    __shared__ float red_max[4], red_sum[4];

    float4 v[4];
    float vmax = -1e30f;
    #pragma unroll
    for (int i = 0; i < 4; i++) v[i] = row4[t + i * 128];
    #pragma unroll
    for (int i = 0; i < 4; i++)
        vmax = fmaxf(vmax, fmaxf(fmaxf(v[i].x, v[i].y), fmaxf(v[i].z, v[i].w)));
    #pragma unroll
    for (int o = 16; o > 0; o >>= 1) vmax = fmaxf(vmax, __shfl_xor_sync(~0u, vmax, o));
    if (lane == 0) red_max[warp] = vmax;
    __syncthreads();
    vmax = fmaxf(fmaxf(red_max[0], red_max[1]), fmaxf(red_max[2], red_max[3]));

    float sum = 0.f;
    #pragma unroll
    for (int i = 0; i < 4; i++) {
        v[i].x = __expf(v[i].x - vmax); v[i].y = __expf(v[i].y - vmax);
        v[i].z = __expf(v[i].z - vmax); v[i].w = __expf(v[i].w - vmax);
        sum += (v[i].x + v[i].y) + (v[i].z + v[i].w);
    }
    #pragma unroll
    for (int o = 16; o > 0; o >>= 1) sum += __shfl_xor_sync(~0u, sum, o);
    if (lane == 0) red_sum[warp] = sum;
    __syncthreads();
    float tot = (red_sum[0] + red_sum[1]) + (red_sum[2] + red_sum[3]);
    float inv = 1.0f / tot;

    uint2* Ph2 = reinterpret_cast<uint2*>(Ph + rowoff);
    #pragma unroll
    for (int i = 0; i < 4; i++) {
        float4 p;
        p.x = v[i].x * inv; p.y = v[i].y * inv;
        p.z = v[i].z * inv; p.w = v[i].w * inv;
        row4[t + i * 128] = p;
        __half2 a = __floats2half2_rn(p.x, p.y), b = __floats2half2_rn(p.z, p.w);
        Ph2[t + i * 128] = make_uint2(*(uint32_t*)&a, *(uint32_t*)&b);
    }
}

// ======================= launch =======================
extern "C" void kernel_launch(void* const* d_in, const int* in_sizes, int n_in,
                              void* d_out, int out_size)
{
    const float* x  = (const float*)d_in[0];
    const float* Wq = (const float*)d_in[1];
    const float* bq = (const float*)d_in[2];
    const float* Wk = (const float*)d_in[3];
    const float* bk = (const float*)d_in[4];
    const float* Wv = (const float*)d_in[5];
    const float* bv = (const float*)d_in[6];

    const int B = 4, S = 2048, D = 512;
    float* att = (float*)d_out;
    float* wtd = att + (size_t)B * S * S;

    __half *Xh, *Wh, *Qh, *Kh, *Vth, *Ph;
    cudaGetSymbolAddress((void**)&Xh, g_Xh);
    cudaGetSymbolAddress((void**)&Wh, g_Wh);
    cudaGetSymbolAddress((void**)&Qh, g_Qh);
    cudaGetSymbolAddress((void**)&Kh, g_Kh);
    cudaGetSymbolAddress((void**)&Vth, g_Vth);
    cudaGetSymbolAddress((void**)&Ph, g_Ph);

    cudaFuncSetAttribute(gemm128<2>, cudaFuncAttributeMaxDynamicSharedMemorySize, SMEM_G);
    cudaFuncSetAttribute(gemm128<3>, cudaFuncAttributeMaxDynamicSharedMemorySize, SMEM_G);

    const int NX4 = B * S * D / 4;       // 1048576
    const int NW4 = D * D / 4;           // 65536
    const int NALL = NX4 + 3 * NW4;
    cvt_all<<<(NALL + 255) / 256, 256>>>(x, Wq, Wk, Wv, Xh, Wh, NX4, NW4);

    // fused QKV projections (1-term fp16): Q, K normal; V transposed into Vth [512, 8192]
    dim3 gqkv(12, 64, 1);
    gemm128<3><<<gqkv, 128, SMEM_G>>>(Xh, Wh, bq, bk, bv, nullptr, Qh, Kh, Vth,
                                      D, D, D, D, 0, 0, 0, 1.0f);

    // scores: att[b] = Q[b] @ K[b]^T * scale
    const float scale = 1.0f / sqrtf((float)D);
    dim3 gsc(S / 128, S / 128, B);
    gemm128<2><<<gsc, 128, SMEM_G>>>(Qh, Kh, nullptr, nullptr, nullptr, att,
                                     nullptr, nullptr, nullptr,
                                     D, D, D, S,
                                     (long)S * D, (long)S * D, (long)S * S, scale);

    // softmax
    softmax_kernel<<<B * S, 128>>>(att, Ph);

    // weighted: wtd[b] = P[b] @ V[b]  (Vt is [512, 8192], per-batch col offset b*2048)
    dim3 gw(D / 128, S / 128, B);
    gemm128<2><<<gw, 128, SMEM_G>>>(Ph, Vth, nullptr, nullptr, nullptr, wtd,
                                    nullptr, nullptr, nullptr,
                                    S, S, 8192, D,
                                    (long)S * S, (long)S, (long)S * D, 1.0f);
}